// round 2
// baseline (speedup 1.0000x reference)
#include <cuda_runtime.h>
#include <cuda_bf16.h>

// Problem constants: B=2, T=2048, D=1024, H=16, dk=64
#define T_LEN 2048
#define D_DIM 1024
#define NHEAD 16
#define DK 64
#define NBH 32          // B*H
#define FPAD 68         // padded row stride (floats) for flash smem tiles

// Scratch: head-major (B,H,T,dk) buffers. 4 x 16MB.
__device__ float g_Qh[4194304];
__device__ float g_Kh[4194304];
__device__ float g_Vh[4194304];
__device__ float g_Oh[4194304];

// ---------------------------------------------------------------------------
// Kernel 1: QKV GEMM (M=4096, N=3072, K=1024) + RoPE + head-major transpose
// out[m,n] = sum_k x[m,k] * w_qkv[n,k]
// ---------------------------------------------------------------------------
__global__ __launch_bounds__(256) void qkv_rope_kernel(
    const float* __restrict__ x, const float* __restrict__ w,
    const float* __restrict__ rope)
{
    __shared__ float As[16][132];   // [k][m] transposed
    __shared__ float Bs[16][132];   // [k][n] transposed

    const int tid = threadIdx.x;
    const int tx = tid & 15, ty = tid >> 4;
    const int m0 = blockIdx.y * 128;
    const int n0 = blockIdx.x * 128;

    float acc[8][8];
#pragma unroll
    for (int i = 0; i < 8; i++)
#pragma unroll
        for (int j = 0; j < 8; j++) acc[i][j] = 0.f;

    const int r = tid >> 2;          // 0..63
    const int c = (tid & 3) * 4;     // 0,4,8,12

    for (int k0 = 0; k0 < 1024; k0 += 16) {
        __syncthreads();
#pragma unroll
        for (int i = 0; i < 2; i++) {
            const int row = i * 64 + r;
            float4 av = *(const float4*)(x + (size_t)(m0 + row) * 1024 + k0 + c);
            As[c+0][row] = av.x; As[c+1][row] = av.y;
            As[c+2][row] = av.z; As[c+3][row] = av.w;
            float4 bv = *(const float4*)(w + (size_t)(n0 + row) * 1024 + k0 + c);
            Bs[c+0][row] = bv.x; Bs[c+1][row] = bv.y;
            Bs[c+2][row] = bv.z; Bs[c+3][row] = bv.w;
        }
        __syncthreads();
#pragma unroll
        for (int kk = 0; kk < 16; kk++) {
            float4 a0 = *(const float4*)&As[kk][ty * 4];
            float4 a1 = *(const float4*)&As[kk][ty * 4 + 64];
            float4 b0 = *(const float4*)&Bs[kk][tx * 4];
            float4 b1 = *(const float4*)&Bs[kk][tx * 4 + 64];
            float am[8] = {a0.x,a0.y,a0.z,a0.w,a1.x,a1.y,a1.z,a1.w};
            float bn[8] = {b0.x,b0.y,b0.z,b0.w,b1.x,b1.y,b1.z,b1.w};
#pragma unroll
            for (int i = 0; i < 8; i++)
#pragma unroll
                for (int j = 0; j < 8; j++) acc[i][j] += am[i] * bn[j];
        }
    }

    // Epilogue: section is uniform per block (tile width 128 divides 1024)
    const int section = n0 >> 10;   // 0=q, 1=k, 2=v
    float* dst_base = (section == 0) ? g_Qh : (section == 1) ? g_Kh : g_Vh;

#pragma unroll
    for (int im = 0; im < 2; im++)
#pragma unroll
    for (int i = 0; i < 4; i++) {
        const int m = m0 + im * 64 + ty * 4 + i;
        const int t = m & 2047;
        const int b = m >> 11;
#pragma unroll
        for (int in_ = 0; in_ < 2; in_++) {
            const int ncol = n0 + in_ * 64 + tx * 4;
            const int nn = ncol & 1023;           // offset within section
            const int h = nn >> 6, d = nn & 63;
            const float v0 = acc[im*4+i][in_*4+0];
            const float v1 = acc[im*4+i][in_*4+1];
            const float v2 = acc[im*4+i][in_*4+2];
            const float v3 = acc[im*4+i][in_*4+3];
            float4 out;
            if (section == 2) {
                out = make_float4(v0, v1, v2, v3);
            } else {
                // rope[t][p][0]=cos, [1]=sin ; pairs are (even,odd) consecutive
                const float2* rp = (const float2*)rope + (size_t)t * 512 + (nn >> 1);
                const float2 cs0 = rp[0];
                const float2 cs1 = rp[1];
                out = make_float4(v0 * cs0.x - v1 * cs0.y,
                                  v0 * cs0.y + v1 * cs0.x,
                                  v2 * cs1.x - v3 * cs1.y,
                                  v2 * cs1.y + v3 * cs1.x);
            }
            *(float4*)(dst_base + (((size_t)b * 16 + h) * 2048 + t) * 64 + d) = out;
        }
    }
}

// ---------------------------------------------------------------------------
// Kernel 2: flash attention fp32. grid=(32 qblocks, 32 bh), 256 threads.
// BQ=BK=64, dk=64. Online softmax, scale = 1/8.
// ---------------------------------------------------------------------------
__global__ __launch_bounds__(256) void flash_kernel()
{
    extern __shared__ float sm[];
    float* Qs = sm;                  // [64 d][FPAD] transposed [d][q]
    float* Ks = Qs + 64 * FPAD;      // [64 d][FPAD] transposed [d][k]
    float* Vs = Ks + 64 * FPAD;      // [64 k][FPAD] natural    [k][d]
    float* Ps = Vs + 64 * FPAD;      // [64 k][FPAD] transposed [k][q]

    const int tid = threadIdx.x;
    const int tx = tid & 15, ty = tid >> 4;
    const int qb = blockIdx.x, bh = blockIdx.y;

    const float* Qb = g_Qh + ((size_t)bh * 2048 + qb * 64) * 64;
    const float* Kb = g_Kh + (size_t)bh * 2048 * 64;
    const float* Vb = g_Vh + (size_t)bh * 2048 * 64;

    // Load Q tile transposed [d][q]
    {
        const int row = tid >> 2;
        const int dc = (tid & 3) * 16;
#pragma unroll
        for (int u = 0; u < 4; u++) {
            float4 v = *(const float4*)(Qb + row * 64 + dc + u * 4);
            Qs[(dc+u*4+0)*FPAD+row] = v.x; Qs[(dc+u*4+1)*FPAD+row] = v.y;
            Qs[(dc+u*4+2)*FPAD+row] = v.z; Qs[(dc+u*4+3)*FPAD+row] = v.w;
        }
    }

    float m_i[4], l_i[4], o[4][4];
#pragma unroll
    for (int i = 0; i < 4; i++) {
        m_i[i] = -1e30f; l_i[i] = 0.f;
#pragma unroll
        for (int j = 0; j < 4; j++) o[i][j] = 0.f;
    }

    for (int kt = 0; kt < 32; kt++) {
        __syncthreads();   // prev PV reads of Ks/Vs/Ps done
        {
            const int row = tid >> 2;
            const int dc = (tid & 3) * 16;
            const float* kp = Kb + (size_t)(kt * 64 + row) * 64 + dc;
#pragma unroll
            for (int u = 0; u < 4; u++) {
                float4 v = *(const float4*)(kp + u * 4);
                Ks[(dc+u*4+0)*FPAD+row] = v.x; Ks[(dc+u*4+1)*FPAD+row] = v.y;
                Ks[(dc+u*4+2)*FPAD+row] = v.z; Ks[(dc+u*4+3)*FPAD+row] = v.w;
            }
            const float* vp = Vb + (size_t)(kt * 64 + row) * 64 + dc;
#pragma unroll
            for (int u = 0; u < 4; u++)
                *(float4*)(Vs + row * FPAD + dc + u * 4) = *(const float4*)(vp + u * 4);
        }
        __syncthreads();

        // S = Q @ K^T  (thread owns q rows ty*4..+3, k cols tx*4..+3)
        float s[4][4];
#pragma unroll
        for (int i = 0; i < 4; i++)
#pragma unroll
            for (int j = 0; j < 4; j++) s[i][j] = 0.f;
#pragma unroll 8
        for (int d = 0; d < 64; d++) {
            float4 a = *(const float4*)&Qs[d * FPAD + ty * 4];
            float4 b = *(const float4*)&Ks[d * FPAD + tx * 4];
            float av[4] = {a.x, a.y, a.z, a.w};
            float bv[4] = {b.x, b.y, b.z, b.w};
#pragma unroll
            for (int i = 0; i < 4; i++)
#pragma unroll
                for (int j = 0; j < 4; j++) s[i][j] += av[i] * bv[j];
        }

        // Online softmax (row reductions across the 16-lane tx group)
#pragma unroll
        for (int i = 0; i < 4; i++) {
#pragma unroll
            for (int j = 0; j < 4; j++) s[i][j] *= 0.125f;
            float mt = fmaxf(fmaxf(s[i][0], s[i][1]), fmaxf(s[i][2], s[i][3]));
#pragma unroll
            for (int off = 8; off > 0; off >>= 1)
                mt = fmaxf(mt, __shfl_xor_sync(0xffffffffu, mt, off));
            const float mnew = fmaxf(m_i[i], mt);
            const float alpha = __expf(m_i[i] - mnew);
            float rs = 0.f;
#pragma unroll
            for (int j = 0; j < 4; j++) {
                s[i][j] = __expf(s[i][j] - mnew);
                rs += s[i][j];
            }
#pragma unroll
            for (int off = 8; off > 0; off >>= 1)
                rs += __shfl_xor_sync(0xffffffffu, rs, off);
            l_i[i] = l_i[i] * alpha + rs;
            m_i[i] = mnew;
#pragma unroll
            for (int j = 0; j < 4; j++) o[i][j] *= alpha;
        }

        // Stage P transposed [k][q]
#pragma unroll
        for (int i = 0; i < 4; i++)
#pragma unroll
            for (int j = 0; j < 4; j++)
                Ps[(tx * 4 + j) * FPAD + ty * 4 + i] = s[i][j];
        __syncthreads();

        // O += P @ V  (thread owns q rows ty*4..+3, d cols tx*4..+3)
#pragma unroll 8
        for (int k = 0; k < 64; k++) {
            float4 p = *(const float4*)&Ps[k * FPAD + ty * 4];
            float4 v = *(const float4*)&Vs[k * FPAD + tx * 4];
            float pa[4] = {p.x, p.y, p.z, p.w};
            float va[4] = {v.x, v.y, v.z, v.w};
#pragma unroll
            for (int i = 0; i < 4; i++)
#pragma unroll
                for (int j = 0; j < 4; j++) o[i][j] += pa[i] * va[j];
        }
    }

    // Epilogue: normalize and store to head-major O
#pragma unroll
    for (int i = 0; i < 4; i++) {
        const float inv = 1.f / l_i[i];
        float4 out = make_float4(o[i][0] * inv, o[i][1] * inv,
                                 o[i][2] * inv, o[i][3] * inv);
        *(float4*)(g_Oh + ((size_t)bh * 2048 + qb * 64 + ty * 4 + i) * 64 + tx * 4) = out;
    }
}

// ---------------------------------------------------------------------------
// Kernel 3: output proj GEMM (M=4096, N=1024, K=1024)
// A read from head-major g_Oh; out[m,n] = sum_k O[m,k] * w_proj[n,k]
// ---------------------------------------------------------------------------
__global__ __launch_bounds__(256) void proj_kernel(
    const float* __restrict__ w, float* __restrict__ out)
{
    __shared__ float As[16][132];
    __shared__ float Bs[16][132];

    const int tid = threadIdx.x;
    const int tx = tid & 15, ty = tid >> 4;
    const int m0 = blockIdx.y * 128;
    const int n0 = blockIdx.x * 128;

    float acc[8][8];
#pragma unroll
    for (int i = 0; i < 8; i++)
#pragma unroll
        for (int j = 0; j < 8; j++) acc[i][j] = 0.f;

    const int r = tid >> 2;
    const int c = (tid & 3) * 4;

    for (int k0 = 0; k0 < 1024; k0 += 16) {
        __syncthreads();
#pragma unroll
        for (int i = 0; i < 2; i++) {
            const int row = i * 64 + r;
            const int m = m0 + row;
            const int t = m & 2047;
            const int b = m >> 11;
            const int k = k0 + c;  // 16B chunk stays within one 64-wide head block
            float4 av = *(const float4*)(g_Oh +
                (((size_t)b * 16 + (k >> 6)) * 2048 + t) * 64 + (k & 63));
            As[c+0][row] = av.x; As[c+1][row] = av.y;
            As[c+2][row] = av.z; As[c+3][row] = av.w;
            float4 bv = *(const float4*)(w + (size_t)(n0 + row) * 1024 + k0 + c);
            Bs[c+0][row] = bv.x; Bs[c+1][row] = bv.y;
            Bs[c+2][row] = bv.z; Bs[c+3][row] = bv.w;
        }
        __syncthreads();
#pragma unroll
        for (int kk = 0; kk < 16; kk++) {
            float4 a0 = *(const float4*)&As[kk][ty * 4];
            float4 a1 = *(const float4*)&As[kk][ty * 4 + 64];
            float4 b0 = *(const float4*)&Bs[kk][tx * 4];
            float4 b1 = *(const float4*)&Bs[kk][tx * 4 + 64];
            float am[8] = {a0.x,a0.y,a0.z,a0.w,a1.x,a1.y,a1.z,a1.w};
            float bn[8] = {b0.x,b0.y,b0.z,b0.w,b1.x,b1.y,b1.z,b1.w};
#pragma unroll
            for (int i = 0; i < 8; i++)
#pragma unroll
                for (int j = 0; j < 8; j++) acc[i][j] += am[i] * bn[j];
        }
    }

#pragma unroll
    for (int im = 0; im < 2; im++)
#pragma unroll
    for (int i = 0; i < 4; i++) {
        const int m = m0 + im * 64 + ty * 4 + i;
#pragma unroll
        for (int in_ = 0; in_ < 2; in_++) {
            const int n = n0 + in_ * 64 + tx * 4;
            float4 outv = make_float4(acc[im*4+i][in_*4+0], acc[im*4+i][in_*4+1],
                                      acc[im*4+i][in_*4+2], acc[im*4+i][in_*4+3]);
            *(float4*)(out + (size_t)m * 1024 + n) = outv;
        }
    }
}

// ---------------------------------------------------------------------------
extern "C" void kernel_launch(void* const* d_in, const int* in_sizes, int n_in,
                              void* d_out, int out_size)
{
    const float* x      = (const float*)d_in[0];   // (2, 2048, 1024)
    const float* rope   = (const float*)d_in[1];   // (2048, 512, 2)
    const float* w_qkv  = (const float*)d_in[2];   // (3072, 1024)
    const float* w_proj = (const float*)d_in[3];   // (1024, 1024)
    float* out = (float*)d_out;                    // (2, 2048, 1024)

    const int flash_smem = 4 * 64 * FPAD * (int)sizeof(float);  // 69632 B
    cudaFuncSetAttribute(flash_kernel,
                         cudaFuncAttributeMaxDynamicSharedMemorySize, flash_smem);

    qkv_rope_kernel<<<dim3(24, 32), 256>>>(x, w_qkv, rope);
    flash_kernel<<<dim3(32, 32), 256, flash_smem>>>();
    proj_kernel<<<dim3(8, 32), 256>>>(w_proj, out);
}

// round 5
// speedup vs baseline: 1.8750x; 1.8750x over previous
#include <cuda_runtime.h>
#include <cuda_bf16.h>
#include <cstdint>

// Problem constants: B=2, T=2048, D=1024, H=16, dk=64
// Scratch: head-major (B,H,T,dk) buffers.
__device__ float g_Qh[4194304];
__device__ float g_Kh[4194304];
__device__ float g_Vh[4194304];
__device__ float g_Oh[4194304];

// ---------------------------------------------------------------------------
// Helpers: bf16 split + mma.sync (HMMA path, valid on plain compute_103)
// ---------------------------------------------------------------------------
__device__ __forceinline__ void split2(float f0, float f1, uint32_t& hi, uint32_t& lo) {
    __nv_bfloat162 h = __floats2bfloat162_rn(f0, f1);   // x=f0 (low), y=f1 (high)
    float r0 = f0 - __bfloat162float(h.x);
    float r1 = f1 - __bfloat162float(h.y);
    __nv_bfloat162 l = __floats2bfloat162_rn(r0, r1);
    hi = *(uint32_t*)&h;
    lo = *(uint32_t*)&l;
}

__device__ __forceinline__ void mma_bf16(float* d, const uint32_t* a, const uint32_t* b) {
    asm volatile(
        "mma.sync.aligned.m16n8k16.row.col.f32.bf16.bf16.f32 "
        "{%0,%1,%2,%3}, {%4,%5,%6,%7}, {%8,%9}, {%0,%1,%2,%3};"
        : "+f"(d[0]), "+f"(d[1]), "+f"(d[2]), "+f"(d[3])
        : "r"(a[0]), "r"(a[1]), "r"(a[2]), "r"(a[3]), "r"(b[0]), "r"(b[1]));
}

// ---------------------------------------------------------------------------
// GEMM: out[m,n] = sum_k A[m,k] * W[n,k]  via split-bf16 (3 mma terms)
// CTA tile 128x128, 8 warps, warp tile 64x32 (4 m16-tiles x 4 n8-tiles).
// K staged 32-wide: fp32 -> hi/lo bf16 pairs in smem.
// MODE 0: A = x row-major; epilogue RoPE + head-major Q/K/V scatter.
// MODE 1: A = g_Oh head-major; epilogue plain store.
// ---------------------------------------------------------------------------
#define WSTRIDE 18   // words per row (16 data words + 2 pad)

template <int MODE>
__global__ __launch_bounds__(256) void mma_gemm_kernel(
    const float* __restrict__ A, const float* __restrict__ W,
    const float* __restrict__ rope, float* __restrict__ out)
{
    __shared__ uint32_t Ahi[128 * WSTRIDE], Alo[128 * WSTRIDE];
    __shared__ uint32_t Bhi[128 * WSTRIDE], Blo[128 * WSTRIDE];

    const int tid = threadIdx.x;
    const int lane = tid & 31;
    const int wid = tid >> 5;
    const int wm = wid & 1;        // 0..1  -> m offset 64*wm
    const int wn = wid >> 1;       // 0..3  -> n offset 32*wn
    const int m0 = blockIdx.y * 128;
    const int n0 = blockIdx.x * 128;

    float acc[4][4][4];
#pragma unroll
    for (int mt = 0; mt < 4; mt++)
#pragma unroll
        for (int nt = 0; nt < 4; nt++)
#pragma unroll
            for (int r = 0; r < 4; r++) acc[mt][nt][r] = 0.f;

    const int srow = tid >> 1;           // 0..127
    const int sc = (tid & 1) * 16;       // 0 or 16

    float4 la[4], lb[4];
    // prologue load (stage 0)
#pragma unroll
    for (int j = 0; j < 4; j++) {
        const int k = sc + 4 * j;
        if (MODE == 0) {
            la[j] = *(const float4*)(A + (size_t)(m0 + srow) * 1024 + k);
        } else {
            const int m = m0 + srow, b = m >> 11, t = m & 2047;
            la[j] = *(const float4*)(g_Oh +
                (((size_t)b * 16 + (k >> 6)) * 2048 + t) * 64 + (k & 63));
        }
        lb[j] = *(const float4*)(W + (size_t)(n0 + srow) * 1024 + k);
    }

    for (int ks = 0; ks < 32; ks++) {
        __syncthreads();
        // store current stage (convert fp32 -> split bf16)
#pragma unroll
        for (int j = 0; j < 4; j++) {
            const int widx = srow * WSTRIDE + sc / 2 + 2 * j;
            uint32_t h0, l0, h1, l1;
            split2(la[j].x, la[j].y, h0, l0);
            split2(la[j].z, la[j].w, h1, l1);
            Ahi[widx] = h0; Ahi[widx + 1] = h1;
            Alo[widx] = l0; Alo[widx + 1] = l1;
            split2(lb[j].x, lb[j].y, h0, l0);
            split2(lb[j].z, lb[j].w, h1, l1);
            Bhi[widx] = h0; Bhi[widx + 1] = h1;
            Blo[widx] = l0; Blo[widx + 1] = l1;
        }
        __syncthreads();
        // prefetch next stage while computing
        if (ks + 1 < 32) {
            const int k0n = (ks + 1) * 32;
#pragma unroll
            for (int j = 0; j < 4; j++) {
                const int k = k0n + sc + 4 * j;
                if (MODE == 0) {
                    la[j] = *(const float4*)(A + (size_t)(m0 + srow) * 1024 + k);
                } else {
                    const int m = m0 + srow, b = m >> 11, t = m & 2047;
                    la[j] = *(const float4*)(g_Oh +
                        (((size_t)b * 16 + (k >> 6)) * 2048 + t) * 64 + (k & 63));
                }
                lb[j] = *(const float4*)(W + (size_t)(n0 + srow) * 1024 + k);
            }
        }
        // compute: 2 k16 chunks
#pragma unroll
        for (int kc = 0; kc < 2; kc++) {
            const int w0 = (lane & 3) + 8 * kc;
            uint32_t afh[4][4], afl[4][4];
#pragma unroll
            for (int mt = 0; mt < 4; mt++) {
                const int row = wm * 64 + mt * 16 + (lane >> 2);
                afh[mt][0] = Ahi[row * WSTRIDE + w0];
                afh[mt][1] = Ahi[(row + 8) * WSTRIDE + w0];
                afh[mt][2] = Ahi[row * WSTRIDE + w0 + 4];
                afh[mt][3] = Ahi[(row + 8) * WSTRIDE + w0 + 4];
                afl[mt][0] = Alo[row * WSTRIDE + w0];
                afl[mt][1] = Alo[(row + 8) * WSTRIDE + w0];
                afl[mt][2] = Alo[row * WSTRIDE + w0 + 4];
                afl[mt][3] = Alo[(row + 8) * WSTRIDE + w0 + 4];
            }
            uint32_t bfh[4][2], bfl[4][2];
#pragma unroll
            for (int nt = 0; nt < 4; nt++) {
                const int n = wn * 32 + nt * 8 + (lane >> 2);
                bfh[nt][0] = Bhi[n * WSTRIDE + w0];
                bfh[nt][1] = Bhi[n * WSTRIDE + w0 + 4];
                bfl[nt][0] = Blo[n * WSTRIDE + w0];
                bfl[nt][1] = Blo[n * WSTRIDE + w0 + 4];
            }
#pragma unroll
            for (int mt = 0; mt < 4; mt++)
#pragma unroll
                for (int nt = 0; nt < 4; nt++) {
                    mma_bf16(acc[mt][nt], afh[mt], bfh[nt]);
                    mma_bf16(acc[mt][nt], afh[mt], bfl[nt]);
                    mma_bf16(acc[mt][nt], afl[mt], bfh[nt]);
                }
        }
    }

    // Epilogue
    const int section = n0 >> 10;   // MODE 0 only: 0=q,1=k,2=v (uniform per CTA)
    float* dstQKV = (section == 0) ? g_Qh : (section == 1) ? g_Kh : g_Vh;
#pragma unroll
    for (int mt = 0; mt < 4; mt++) {
#pragma unroll
        for (int nt = 0; nt < 4; nt++) {
            const int cn = n0 + wn * 32 + nt * 8 + 2 * (lane & 3);
#pragma unroll
            for (int rr = 0; rr < 2; rr++) {
                const int m = m0 + wm * 64 + mt * 16 + (lane >> 2) + 8 * rr;
                const float v0 = acc[mt][nt][2 * rr];
                const float v1 = acc[mt][nt][2 * rr + 1];
                if (MODE == 0) {
                    const int t = m & 2047, b = m >> 11;
                    const int nn = cn & 1023;
                    float2 o;
                    if (section == 2) {
                        o = make_float2(v0, v1);
                    } else {
                        const float2 cs = ((const float2*)rope)[(size_t)t * 512 + (nn >> 1)];
                        o = make_float2(v0 * cs.x - v1 * cs.y, v0 * cs.y + v1 * cs.x);
                    }
                    *(float2*)(dstQKV +
                        (((size_t)b * 16 + (nn >> 6)) * 2048 + t) * 64 + (nn & 63)) = o;
                } else {
                    *(float2*)(out + (size_t)m * 1024 + cn) = make_float2(v0, v1);
                }
            }
        }
    }
}

// ---------------------------------------------------------------------------
// Flash attention via mma.sync, split-bf16. BQ=128, BK=64, dk=64.
// 8 warps; warp owns m16 q-rows. Q fragments register-resident (scaled 1/8).
// K staged [tok][d] split-bf16; V staged transposed [d][tokpair].
// grid = (16 qblocks, 32 bh), 256 threads.
// ---------------------------------------------------------------------------
#define VSTRIDE 34   // words per row (32 data + 2 pad)

__global__ __launch_bounds__(256) void flash_mma_kernel()
{
    __shared__ uint32_t Khi[64 * VSTRIDE], Klo[64 * VSTRIDE];
    __shared__ uint32_t Vhi[64 * VSTRIDE], Vlo[64 * VSTRIDE];

    const int tid = threadIdx.x;
    const int lane = tid & 31;
    const int w = tid >> 5;
    const int qb = blockIdx.x, bh = blockIdx.y;

    const float* Qb = g_Qh + ((size_t)bh * 2048 + qb * 128) * 64;
    const float* Kb = g_Kh + (size_t)bh * 2048 * 64;
    const float* Vb = g_Vh + (size_t)bh * 2048 * 64;

    // Q fragments (scale 1/8 folded in — exact power of 2)
    uint32_t qh[4][4], ql[4][4];
    {
        const int r0 = w * 16 + (lane >> 2);
#pragma unroll
        for (int kc = 0; kc < 4; kc++)
#pragma unroll
            for (int u = 0; u < 2; u++) {
                const int c = 16 * kc + 2 * (lane & 3) + 8 * u;
                float2 v0 = *(const float2*)(Qb + (size_t)r0 * 64 + c);
                float2 v1 = *(const float2*)(Qb + (size_t)(r0 + 8) * 64 + c);
                split2(v0.x * 0.125f, v0.y * 0.125f, qh[kc][2 * u], ql[kc][2 * u]);
                split2(v1.x * 0.125f, v1.y * 0.125f, qh[kc][2 * u + 1], ql[kc][2 * u + 1]);
            }
    }

    float m0_ = -1e30f, m1_ = -1e30f, l0_ = 0.f, l1_ = 0.f;
    float o[8][4];
#pragma unroll
    for (int nt = 0; nt < 8; nt++)
#pragma unroll
        for (int r = 0; r < 4; r++) o[nt][r] = 0.f;

    for (int kt = 0; kt < 32; kt++) {
        __syncthreads();
        // ---- stage K (split bf16, [tok][d-pairs]) ----
        {
            const int tok = tid >> 2;
            const int c4 = (tid & 3) * 16;
            const float* kp = Kb + ((size_t)(kt * 64 + tok)) * 64 + c4;
#pragma unroll
            for (int j = 0; j < 4; j++) {
                float4 v = *(const float4*)(kp + 4 * j);
                uint32_t h0, l0w, h1, l1w;
                split2(v.x, v.y, h0, l0w);
                split2(v.z, v.w, h1, l1w);
                const int widx = tok * VSTRIDE + c4 / 2 + 2 * j;
                Khi[widx] = h0; Khi[widx + 1] = h1;
                Klo[widx] = l0w; Klo[widx + 1] = l1w;
            }
            // ---- stage V transposed ([d][tok-pairs]) ----
            const int d = tid & 63;
            const int tpb = (tid >> 6) * 8;
            const float* vp = Vb + ((size_t)(kt * 64)) * 64 + d;
#pragma unroll
            for (int i = 0; i < 8; i++) {
                const int tp = tpb + i;
                const float a = vp[(size_t)(2 * tp) * 64];
                const float b = vp[(size_t)(2 * tp + 1) * 64];
                uint32_t hw, lw;
                split2(a, b, hw, lw);
                Vhi[d * VSTRIDE + tp] = hw;
                Vlo[d * VSTRIDE + tp] = lw;
            }
        }
        __syncthreads();

        // ---- S = (Q/8) @ K^T ----
        float s[8][4];
#pragma unroll
        for (int nt = 0; nt < 8; nt++)
#pragma unroll
            for (int r = 0; r < 4; r++) s[nt][r] = 0.f;
#pragma unroll
        for (int kc = 0; kc < 4; kc++) {
            const int w0 = (lane & 3) + 8 * kc;
#pragma unroll
            for (int nt = 0; nt < 8; nt++) {
                const int n = nt * 8 + (lane >> 2);
                uint32_t bh_[2] = { Khi[n * VSTRIDE + w0], Khi[n * VSTRIDE + w0 + 4] };
                uint32_t bl_[2] = { Klo[n * VSTRIDE + w0], Klo[n * VSTRIDE + w0 + 4] };
                mma_bf16(s[nt], qh[kc], bh_);
                mma_bf16(s[nt], qh[kc], bl_);
                mma_bf16(s[nt], ql[kc], bh_);
            }
        }

        // ---- online softmax (rows l/4 and l/4+8; quad = lanes sharing l>>2) ----
        float ml0 = -1e30f, ml1 = -1e30f;
#pragma unroll
        for (int nt = 0; nt < 8; nt++) {
            ml0 = fmaxf(ml0, fmaxf(s[nt][0], s[nt][1]));
            ml1 = fmaxf(ml1, fmaxf(s[nt][2], s[nt][3]));
        }
#pragma unroll
        for (int off = 1; off <= 2; off <<= 1) {
            ml0 = fmaxf(ml0, __shfl_xor_sync(0xffffffffu, ml0, off));
            ml1 = fmaxf(ml1, __shfl_xor_sync(0xffffffffu, ml1, off));
        }
        const float mn0 = fmaxf(m0_, ml0), mn1 = fmaxf(m1_, ml1);
        const float a0 = __expf(m0_ - mn0), a1 = __expf(m1_ - mn1);
        m0_ = mn0; m1_ = mn1;
        float rs0 = 0.f, rs1 = 0.f;
#pragma unroll
        for (int nt = 0; nt < 8; nt++) {
            s[nt][0] = __expf(s[nt][0] - mn0);
            s[nt][1] = __expf(s[nt][1] - mn0);
            s[nt][2] = __expf(s[nt][2] - mn1);
            s[nt][3] = __expf(s[nt][3] - mn1);
            rs0 += s[nt][0] + s[nt][1];
            rs1 += s[nt][2] + s[nt][3];
        }
#pragma unroll
        for (int off = 1; off <= 2; off <<= 1) {
            rs0 += __shfl_xor_sync(0xffffffffu, rs0, off);
            rs1 += __shfl_xor_sync(0xffffffffu, rs1, off);
        }
        l0_ = l0_ * a0 + rs0;
        l1_ = l1_ * a1 + rs1;
#pragma unroll
        for (int nt = 0; nt < 8; nt++) {
            o[nt][0] *= a0; o[nt][1] *= a0;
            o[nt][2] *= a1; o[nt][3] *= a1;
        }

        // ---- P fragments (S-frag layout == A-operand layout; pure packing) ----
        uint32_t ph[4][4], pl[4][4];
#pragma unroll
        for (int kc = 0; kc < 4; kc++) {
            split2(s[2 * kc][0], s[2 * kc][1], ph[kc][0], pl[kc][0]);
            split2(s[2 * kc][2], s[2 * kc][3], ph[kc][1], pl[kc][1]);
            split2(s[2 * kc + 1][0], s[2 * kc + 1][1], ph[kc][2], pl[kc][2]);
            split2(s[2 * kc + 1][2], s[2 * kc + 1][3], ph[kc][3], pl[kc][3]);
        }

        // ---- O += P @ V ----
#pragma unroll
        for (int kc = 0; kc < 4; kc++) {
            const int w0 = (lane & 3) + 8 * kc;
#pragma unroll
            for (int nt = 0; nt < 8; nt++) {
                const int d = nt * 8 + (lane >> 2);
                uint32_t bhv[2] = { Vhi[d * VSTRIDE + w0], Vhi[d * VSTRIDE + w0 + 4] };
                uint32_t blv[2] = { Vlo[d * VSTRIDE + w0], Vlo[d * VSTRIDE + w0 + 4] };
                mma_bf16(o[nt], ph[kc], bhv);
                mma_bf16(o[nt], ph[kc], blv);
                mma_bf16(o[nt], pl[kc], bhv);
            }
        }
    }

    // ---- normalize + store ----
    const float inv0 = 1.f / l0_, inv1 = 1.f / l1_;
    const int qrow = qb * 128 + w * 16 + (lane >> 2);
    float* Ob = g_Oh + ((size_t)bh * 2048 + qrow) * 64;
#pragma unroll
    for (int nt = 0; nt < 8; nt++) {
        const int c = nt * 8 + 2 * (lane & 3);
        *(float2*)(Ob + c) = make_float2(o[nt][0] * inv0, o[nt][1] * inv0);
        *(float2*)(Ob + (size_t)8 * 64 + c) = make_float2(o[nt][2] * inv1, o[nt][3] * inv1);
    }
}

// ---------------------------------------------------------------------------
extern "C" void kernel_launch(void* const* d_in, const int* in_sizes, int n_in,
                              void* d_out, int out_size)
{
    const float* x      = (const float*)d_in[0];   // (2, 2048, 1024)
    const float* rope   = (const float*)d_in[1];   // (2048, 512, 2)
    const float* w_qkv  = (const float*)d_in[2];   // (3072, 1024)
    const float* w_proj = (const float*)d_in[3];   // (1024, 1024)
    float* out = (float*)d_out;                    // (2, 2048, 1024)

    mma_gemm_kernel<0><<<dim3(24, 32), 256>>>(x, w_qkv, rope, nullptr);
    flash_mma_kernel<<<dim3(16, 32), 256>>>();
    mma_gemm_kernel<1><<<dim3(8, 32), 256>>>(nullptr, w_proj, nullptr, out);
}

// round 6
// speedup vs baseline: 2.4408x; 1.3018x over previous
#include <cuda_runtime.h>
#include <cuda_bf16.h>
#include <cstdint>

// Problem constants: B=2, T=2048, D=1024, H=16, dk=64
// Scratch: head-major (B,H,T,dk).
__device__ float    g_Oh[4194304];                    // attention out, fp32
__device__ uint32_t g_Qhi[2097152], g_Qlo[2097152];   // split-bf16 pairs (words)
__device__ uint32_t g_Khi[2097152], g_Klo[2097152];
__device__ uint32_t g_Vhi[2097152], g_Vlo[2097152];

// ---------------------------------------------------------------------------
// Helpers
// ---------------------------------------------------------------------------
__device__ __forceinline__ void split2(float f0, float f1, uint32_t& hi, uint32_t& lo) {
    __nv_bfloat162 h = __floats2bfloat162_rn(f0, f1);
    float r0 = f0 - __bfloat162float(h.x);
    float r1 = f1 - __bfloat162float(h.y);
    __nv_bfloat162 l = __floats2bfloat162_rn(r0, r1);
    hi = *(uint32_t*)&h;
    lo = *(uint32_t*)&l;
}

__device__ __forceinline__ void mma_bf16(float* d, const uint32_t* a, const uint32_t* b) {
    asm volatile(
        "mma.sync.aligned.m16n8k16.row.col.f32.bf16.bf16.f32 "
        "{%0,%1,%2,%3}, {%4,%5,%6,%7}, {%8,%9}, {%0,%1,%2,%3};"
        : "+f"(d[0]), "+f"(d[1]), "+f"(d[2]), "+f"(d[3])
        : "r"(a[0]), "r"(a[1]), "r"(a[2]), "r"(a[3]), "r"(b[0]), "r"(b[1]));
}

__device__ __forceinline__ void ldm_x4(uint32_t* r, uint32_t addr) {
    asm volatile("ldmatrix.sync.aligned.m8n8.x4.shared.b16 {%0,%1,%2,%3}, [%4];"
                 : "=r"(r[0]), "=r"(r[1]), "=r"(r[2]), "=r"(r[3]) : "r"(addr));
}
__device__ __forceinline__ void ldm_x4t(uint32_t* r, uint32_t addr) {
    asm volatile("ldmatrix.sync.aligned.m8n8.x4.trans.shared.b16 {%0,%1,%2,%3}, [%4];"
                 : "=r"(r[0]), "=r"(r[1]), "=r"(r[2]), "=r"(r[3]) : "r"(addr));
}
__device__ __forceinline__ uint32_t smem_addr(const void* p) {
    return (uint32_t)__cvta_generic_to_shared(p);
}

// ---------------------------------------------------------------------------
// GEMM: out[m,n] = sum_k A[m,k]*W[n,k], split-bf16 (3 mma terms).
// CTA 128x128, 8 warps (warp tile 64x32). Shared tiles stride 20 words
// (conflict-free ldmatrix: 20n mod 32 = {0,20,8,28,16,4,24,12}).
// MODE 0: A = x; epilogue RoPE + split-bf16 Q/K/V store (Q scaled 1/8).
// MODE 1: A = g_Oh (head-major); epilogue fp32 store to out.
// ---------------------------------------------------------------------------
#define GS 20

template <int MODE>
__global__ __launch_bounds__(256) void mma_gemm_kernel(
    const float* __restrict__ A, const float* __restrict__ W,
    const float* __restrict__ rope, float* __restrict__ out)
{
    __shared__ uint32_t Ahi[128 * GS], Alo[128 * GS];
    __shared__ uint32_t Bhi[128 * GS], Blo[128 * GS];

    const int tid = threadIdx.x;
    const int lane = tid & 31;
    const int wid = tid >> 5;
    const int wm = wid & 1;        // m offset 64*wm
    const int wn = wid >> 1;       // n offset 32*wn
    const int m0 = blockIdx.y * 128;
    const int n0 = blockIdx.x * 128;

    float acc[4][4][4];
#pragma unroll
    for (int mt = 0; mt < 4; mt++)
#pragma unroll
        for (int nt = 0; nt < 4; nt++)
#pragma unroll
            for (int r = 0; r < 4; r++) acc[mt][nt][r] = 0.f;

    // ldmatrix lane-offset precompute (in words)
    const int l8 = lane & 7, g = lane >> 3;
    const int offA = (l8 + ((g & 1) << 3)) * GS + ((g & 2) ? 4 : 0);
    const int offB = (l8 + ((g >> 1) << 3)) * GS + ((g & 1) << 2);
    const uint32_t aAhi = smem_addr(Ahi), aAlo = smem_addr(Alo);
    const uint32_t aBhi = smem_addr(Bhi), aBlo = smem_addr(Blo);

    const int srow = tid >> 1;           // 0..127
    const int sc = (tid & 1) * 16;       // 0 or 16 (floats)

    float4 la[4], lb[4];
#pragma unroll
    for (int j = 0; j < 4; j++) {
        const int k = sc + 4 * j;
        if (MODE == 0) {
            la[j] = *(const float4*)(A + (size_t)(m0 + srow) * 1024 + k);
        } else {
            const int m = m0 + srow, b = m >> 11, t = m & 2047;
            la[j] = *(const float4*)(g_Oh +
                (((size_t)b * 16 + (k >> 6)) * 2048 + t) * 64 + (k & 63));
        }
        lb[j] = *(const float4*)(W + (size_t)(n0 + srow) * 1024 + k);
    }

    for (int ks = 0; ks < 32; ks++) {
        __syncthreads();
#pragma unroll
        for (int j = 0; j < 4; j++) {
            const int widx = srow * GS + sc / 2 + 2 * j;
            uint32_t h0, l0, h1, l1;
            split2(la[j].x, la[j].y, h0, l0);
            split2(la[j].z, la[j].w, h1, l1);
            Ahi[widx] = h0; Ahi[widx + 1] = h1;
            Alo[widx] = l0; Alo[widx + 1] = l1;
            split2(lb[j].x, lb[j].y, h0, l0);
            split2(lb[j].z, lb[j].w, h1, l1);
            Bhi[widx] = h0; Bhi[widx + 1] = h1;
            Blo[widx] = l0; Blo[widx + 1] = l1;
        }
        __syncthreads();
        if (ks + 1 < 32) {
            const int k0n = (ks + 1) * 32;
#pragma unroll
            for (int j = 0; j < 4; j++) {
                const int k = k0n + sc + 4 * j;
                if (MODE == 0) {
                    la[j] = *(const float4*)(A + (size_t)(m0 + srow) * 1024 + k);
                } else {
                    const int m = m0 + srow, b = m >> 11, t = m & 2047;
                    la[j] = *(const float4*)(g_Oh +
                        (((size_t)b * 16 + (k >> 6)) * 2048 + t) * 64 + (k & 63));
                }
                lb[j] = *(const float4*)(W + (size_t)(n0 + srow) * 1024 + k);
            }
        }
#pragma unroll
        for (int kc = 0; kc < 2; kc++) {
            uint32_t afh[4][4], afl[4][4];
#pragma unroll
            for (int mt = 0; mt < 4; mt++) {
                const uint32_t wo = 4u * (offA + (wm * 64 + mt * 16) * GS + 8 * kc);
                ldm_x4(afh[mt], aAhi + wo);
                ldm_x4(afl[mt], aAlo + wo);
            }
#pragma unroll
            for (int ntp = 0; ntp < 2; ntp++) {
                uint32_t bhf[4], blf[4];
                const uint32_t wo = 4u * (offB + (wn * 32 + ntp * 16) * GS + 8 * kc);
                ldm_x4(bhf, aBhi + wo);
                ldm_x4(blf, aBlo + wo);
#pragma unroll
                for (int mt = 0; mt < 4; mt++) {
                    mma_bf16(acc[mt][2 * ntp], afh[mt], bhf);
                    mma_bf16(acc[mt][2 * ntp], afh[mt], blf);
                    mma_bf16(acc[mt][2 * ntp], afl[mt], bhf);
                    mma_bf16(acc[mt][2 * ntp + 1], afh[mt], bhf + 2);
                    mma_bf16(acc[mt][2 * ntp + 1], afh[mt], blf + 2);
                    mma_bf16(acc[mt][2 * ntp + 1], afl[mt], bhf + 2);
                }
            }
        }
    }

    // Epilogue
    const int section = n0 >> 10;
    uint32_t* hiArr = (section == 0) ? g_Qhi : (section == 1) ? g_Khi : g_Vhi;
    uint32_t* loArr = (section == 0) ? g_Qlo : (section == 1) ? g_Klo : g_Vlo;
    const float qscale = (section == 0) ? 0.125f : 1.0f;
#pragma unroll
    for (int mt = 0; mt < 4; mt++) {
#pragma unroll
        for (int nt = 0; nt < 4; nt++) {
            const int cn = n0 + wn * 32 + nt * 8 + 2 * (lane & 3);
#pragma unroll
            for (int rr = 0; rr < 2; rr++) {
                const int m = m0 + wm * 64 + mt * 16 + (lane >> 2) + 8 * rr;
                const float v0 = acc[mt][nt][2 * rr];
                const float v1 = acc[mt][nt][2 * rr + 1];
                if (MODE == 0) {
                    const int t = m & 2047, b = m >> 11;
                    const int nn = cn & 1023;
                    float2 o;
                    if (section == 2) {
                        o = make_float2(v0, v1);
                    } else {
                        const float2 cs = ((const float2*)rope)[(size_t)t * 512 + (nn >> 1)];
                        o = make_float2(v0 * cs.x - v1 * cs.y, v0 * cs.y + v1 * cs.x);
                    }
                    uint32_t hw, lw;
                    split2(o.x * qscale, o.y * qscale, hw, lw);
                    const size_t widx =
                        ((((size_t)b * 16 + (nn >> 6)) * 2048 + t) * 64 + (nn & 63)) >> 1;
                    hiArr[widx] = hw;
                    loArr[widx] = lw;
                } else {
                    *(float2*)(out + (size_t)m * 1024 + cn) = make_float2(v0, v1);
                }
            }
        }
    }
}

// ---------------------------------------------------------------------------
// Flash attention, split-bf16 mma. BQ=128 (8 warps x m16), BK=64, dk=64.
// Q frags loaded directly from global (pre-scaled by 1/8).
// K/V tiles staged by pure uint4 copies; stride 36 words (ldmatrix-clean).
// V fragments via ldmatrix.x4.trans (no transposed staging).
// grid = (16 qblocks, 32 bh), 256 threads.
// ---------------------------------------------------------------------------
#define FS 36

__global__ __launch_bounds__(256) void flash_mma_kernel()
{
    __shared__ uint32_t Khi[64 * FS], Klo[64 * FS];
    __shared__ uint32_t Vhi[64 * FS], Vlo[64 * FS];

    const int tid = threadIdx.x;
    const int lane = tid & 31;
    const int w = tid >> 5;
    const int qb = blockIdx.x, bh = blockIdx.y;

    const int l8 = lane & 7, g = lane >> 3;
    // K (B-operand, rows = tokens): m0/m1 same rows + word split, m2/m3 rows+8
    const int offK = (l8 + ((g >> 1) << 3)) * FS + ((g & 1) << 2);
    // V (trans): m0 rows, m1 rows+8, m2/m3 next d-tile
    const int offV = (l8 + ((g & 1) << 3)) * FS + ((g >> 1) << 2);
    const uint32_t aKhi = smem_addr(Khi), aKlo = smem_addr(Klo);
    const uint32_t aVhi = smem_addr(Vhi), aVlo = smem_addr(Vlo);

    // ---- Q fragments from global (rows: w*16 + lane>>2, +8) ----
    uint32_t qh[4][4], ql[4][4];
    {
        const size_t qbase = ((size_t)bh * 2048 + qb * 128) * 32;
        const int r0 = w * 16 + (lane >> 2);
#pragma unroll
        for (int kc = 0; kc < 4; kc++) {
            const int wrd = 8 * kc + (lane & 3);
            qh[kc][0] = g_Qhi[qbase + (size_t)r0 * 32 + wrd];
            qh[kc][1] = g_Qhi[qbase + (size_t)(r0 + 8) * 32 + wrd];
            qh[kc][2] = g_Qhi[qbase + (size_t)r0 * 32 + wrd + 4];
            qh[kc][3] = g_Qhi[qbase + (size_t)(r0 + 8) * 32 + wrd + 4];
            ql[kc][0] = g_Qlo[qbase + (size_t)r0 * 32 + wrd];
            ql[kc][1] = g_Qlo[qbase + (size_t)(r0 + 8) * 32 + wrd];
            ql[kc][2] = g_Qlo[qbase + (size_t)r0 * 32 + wrd + 4];
            ql[kc][3] = g_Qlo[qbase + (size_t)(r0 + 8) * 32 + wrd + 4];
        }
    }

    float m0_ = -1e30f, m1_ = -1e30f, l0_ = 0.f, l1_ = 0.f;
    float o[8][4];
#pragma unroll
    for (int nt = 0; nt < 8; nt++)
#pragma unroll
        for (int r = 0; r < 4; r++) o[nt][r] = 0.f;

    const int cr = tid >> 2;          // copy row 0..63
    const int cq = tid & 3;           // word group

    for (int kt = 0; kt < 32; kt++) {
        __syncthreads();
        {
            const size_t base = ((size_t)bh * 2048 + kt * 64) * 32;
            const size_t gw = base + (size_t)cr * 32 + 8 * cq;
            const int sw = cr * FS + 8 * cq;
            *(uint4*)&Khi[sw]     = *(const uint4*)&g_Khi[gw];
            *(uint4*)&Khi[sw + 4] = *(const uint4*)&g_Khi[gw + 4];
            *(uint4*)&Klo[sw]     = *(const uint4*)&g_Klo[gw];
            *(uint4*)&Klo[sw + 4] = *(const uint4*)&g_Klo[gw + 4];
            *(uint4*)&Vhi[sw]     = *(const uint4*)&g_Vhi[gw];
            *(uint4*)&Vhi[sw + 4] = *(const uint4*)&g_Vhi[gw + 4];
            *(uint4*)&Vlo[sw]     = *(const uint4*)&g_Vlo[gw];
            *(uint4*)&Vlo[sw + 4] = *(const uint4*)&g_Vlo[gw + 4];
        }
        __syncthreads();

        // ---- S = (Q/8) @ K^T ----
        float s[8][4];
#pragma unroll
        for (int nt = 0; nt < 8; nt++)
#pragma unroll
            for (int r = 0; r < 4; r++) s[nt][r] = 0.f;
#pragma unroll
        for (int kc = 0; kc < 4; kc++) {
#pragma unroll
            for (int ntp = 0; ntp < 4; ntp++) {
                uint32_t bhf[4], blf[4];
                const uint32_t wo = 4u * (offK + ntp * 16 * FS + 8 * kc);
                ldm_x4(bhf, aKhi + wo);
                ldm_x4(blf, aKlo + wo);
                mma_bf16(s[2 * ntp], qh[kc], bhf);
                mma_bf16(s[2 * ntp], qh[kc], blf);
                mma_bf16(s[2 * ntp], ql[kc], bhf);
                mma_bf16(s[2 * ntp + 1], qh[kc], bhf + 2);
                mma_bf16(s[2 * ntp + 1], qh[kc], blf + 2);
                mma_bf16(s[2 * ntp + 1], ql[kc], bhf + 2);
            }
        }

        // ---- online softmax ----
        float ml0 = -1e30f, ml1 = -1e30f;
#pragma unroll
        for (int nt = 0; nt < 8; nt++) {
            ml0 = fmaxf(ml0, fmaxf(s[nt][0], s[nt][1]));
            ml1 = fmaxf(ml1, fmaxf(s[nt][2], s[nt][3]));
        }
#pragma unroll
        for (int off = 1; off <= 2; off <<= 1) {
            ml0 = fmaxf(ml0, __shfl_xor_sync(0xffffffffu, ml0, off));
            ml1 = fmaxf(ml1, __shfl_xor_sync(0xffffffffu, ml1, off));
        }
        const float mn0 = fmaxf(m0_, ml0), mn1 = fmaxf(m1_, ml1);
        const float a0 = __expf(m0_ - mn0), a1 = __expf(m1_ - mn1);
        m0_ = mn0; m1_ = mn1;
        float rs0 = 0.f, rs1 = 0.f;
#pragma unroll
        for (int nt = 0; nt < 8; nt++) {
            s[nt][0] = __expf(s[nt][0] - mn0);
            s[nt][1] = __expf(s[nt][1] - mn0);
            s[nt][2] = __expf(s[nt][2] - mn1);
            s[nt][3] = __expf(s[nt][3] - mn1);
            rs0 += s[nt][0] + s[nt][1];
            rs1 += s[nt][2] + s[nt][3];
        }
#pragma unroll
        for (int off = 1; off <= 2; off <<= 1) {
            rs0 += __shfl_xor_sync(0xffffffffu, rs0, off);
            rs1 += __shfl_xor_sync(0xffffffffu, rs1, off);
        }
        l0_ = l0_ * a0 + rs0;
        l1_ = l1_ * a1 + rs1;
#pragma unroll
        for (int nt = 0; nt < 8; nt++) {
            o[nt][0] *= a0; o[nt][1] *= a0;
            o[nt][2] *= a1; o[nt][3] *= a1;
        }

        // ---- P fragments (in-register: S layout == A layout) ----
        uint32_t ph[4][4], pl[4][4];
#pragma unroll
        for (int kc = 0; kc < 4; kc++) {
            split2(s[2 * kc][0], s[2 * kc][1], ph[kc][0], pl[kc][0]);
            split2(s[2 * kc][2], s[2 * kc][3], ph[kc][1], pl[kc][1]);
            split2(s[2 * kc + 1][0], s[2 * kc + 1][1], ph[kc][2], pl[kc][2]);
            split2(s[2 * kc + 1][2], s[2 * kc + 1][3], ph[kc][3], pl[kc][3]);
        }

        // ---- O += P @ V (V via ldmatrix.trans) ----
#pragma unroll
        for (int kc = 0; kc < 4; kc++) {
#pragma unroll
            for (int ntp = 0; ntp < 4; ntp++) {
                uint32_t vhf[4], vlf[4];
                const uint32_t wo = 4u * (offV + kc * 16 * FS + ntp * 8);
                ldm_x4t(vhf, aVhi + wo);
                ldm_x4t(vlf, aVlo + wo);
                mma_bf16(o[2 * ntp], ph[kc], vhf);
                mma_bf16(o[2 * ntp], ph[kc], vlf);
                mma_bf16(o[2 * ntp], pl[kc], vhf);
                mma_bf16(o[2 * ntp + 1], ph[kc], vhf + 2);
                mma_bf16(o[2 * ntp + 1], ph[kc], vlf + 2);
                mma_bf16(o[2 * ntp + 1], pl[kc], vhf + 2);
            }
        }
    }

    // ---- normalize + store (fp32 head-major for proj) ----
    const float inv0 = 1.f / l0_, inv1 = 1.f / l1_;
    const int qrow = qb * 128 + w * 16 + (lane >> 2);
    float* Ob = g_Oh + ((size_t)bh * 2048 + qrow) * 64;
#pragma unroll
    for (int nt = 0; nt < 8; nt++) {
        const int c = nt * 8 + 2 * (lane & 3);
        *(float2*)(Ob + c) = make_float2(o[nt][0] * inv0, o[nt][1] * inv0);
        *(float2*)(Ob + (size_t)8 * 64 + c) = make_float2(o[nt][2] * inv1, o[nt][3] * inv1);
    }
}

// ---------------------------------------------------------------------------
extern "C" void kernel_launch(void* const* d_in, const int* in_sizes, int n_in,
                              void* d_out, int out_size)
{
    const float* x      = (const float*)d_in[0];   // (2, 2048, 1024)
    const float* rope   = (const float*)d_in[1];   // (2048, 512, 2)
    const float* w_qkv  = (const float*)d_in[2];   // (3072, 1024)
    const float* w_proj = (const float*)d_in[3];   // (1024, 1024)
    float* out = (float*)d_out;                    // (2, 2048, 1024)

    mma_gemm_kernel<0><<<dim3(24, 32), 256>>>(x, w_qkv, rope, nullptr);
    flash_mma_kernel<<<dim3(16, 32), 256>>>();
    mma_gemm_kernel<1><<<dim3(8, 32), 256>>>(nullptr, w_proj, nullptr, out);
}